// round 2
// baseline (speedup 1.0000x reference)
#include <cuda_runtime.h>
#include <math.h>
#include <stddef.h>

// ---------------- scratch (device globals; no allocations allowed) ----------
__device__ float g_h  [1024 * 256];
__device__ float g_hi [1024 * 256];
__device__ float g_hj [1024 * 256];
__device__ float g_agg[1024 * 256];
__device__ float g_n1 [1024 * 256];
__device__ float g_n2 [1024 * 256];
__device__ float g_enc[1024 * 256];
__device__ float g_k  [1024 * 256];
__device__ float g_v  [1024 * 256];
__device__ float g_q  [64 * 256];
__device__ float g_oA [64 * 256];
__device__ float g_m1 [64 * 256];
__device__ float g_m2 [64 * 256];

// ---------------- generic tiled GEMM: C = res? res + act(A@W + b) -----------
// A: (M,K) row-major, W: (K,N) row-major, C: (M,N). act: 0=none, 1=relu.
__global__ void gemm_kernel(const float* __restrict__ A, const float* __restrict__ W,
                            const float* __restrict__ bias, const float* __restrict__ res,
                            float* __restrict__ C, int M, int K, int N, int act)
{
    __shared__ float As[32 * 33];
    __shared__ float Ws[32 * 33];
    const int tid  = threadIdx.x;
    const int lane = tid & 31;
    const int ty   = tid >> 5;               // 0..7
    const int colB = blockIdx.x * 32;
    const int rowB = blockIdx.y * 32;

    float acc[4] = {0.f, 0.f, 0.f, 0.f};

    for (int k0 = 0; k0 < K; k0 += 32) {
        #pragma unroll
        for (int u = 0; u < 4; ++u) {
            int idx = tid + u * 256;          // 0..1023
            int r = idx >> 5, c = idx & 31;
            int gr = rowB + r, gk = k0 + c;
            As[r * 33 + c] = (gr < M && gk < K) ? A[(size_t)gr * K + gk] : 0.f;
            int wk = k0 + r, wc = colB + c;
            Ws[r * 33 + c] = (wk < K && wc < N) ? W[(size_t)wk * N + wc] : 0.f;
        }
        __syncthreads();
        #pragma unroll
        for (int kk = 0; kk < 32; ++kk) {
            float wv = Ws[kk * 33 + lane];
            #pragma unroll
            for (int r = 0; r < 4; ++r)
                acc[r] = fmaf(As[(ty * 4 + r) * 33 + kk], wv, acc[r]);
        }
        __syncthreads();
    }

    int col = colB + lane;
    if (col < N) {
        float bv = bias ? bias[col] : 0.f;
        #pragma unroll
        for (int r = 0; r < 4; ++r) {
            int row = rowB + ty * 4 + r;
            if (row < M) {
                float v = acc[r] + bv;
                if (act) v = fmaxf(v, 0.f);
                if (res) v += res[(size_t)row * N + col];
                C[(size_t)row * N + col] = v;
            }
        }
    }
}

// ---------------- fused edge-MLP + adjacency contraction --------------------
// For fixed (b,i): A[j,k] = relu(hi[b,i,k] + hjp[b,j,k])   (geb1 folded into hjp)
//                  Y      = A @ W2[:, hb*64 : hb*64+64]
//                  agg[b,i,h] += sum_j adj[b,i,j] * relu(Y[j,h] + b2[h])
// grid: (hb=4, i=256, b=4); 256 threads; block computes 256(j) x 64(h) tile.
__global__ void __launch_bounds__(256, 2)
edge_kernel(const float* __restrict__ hi, const float* __restrict__ hjp,
            const float* __restrict__ W2, const float* __restrict__ b2,
            const float* __restrict__ adj, float* __restrict__ agg)
{
    __shared__ float ci[256];
    __shared__ float adjrow[256];
    __shared__ float A_s[256 * 33];     // [j][k], pitch 33 (conflict-free bcast reads)
    __shared__ float B_s[32 * 64];      // [k][h]

    const int tid = threadIdx.x;
    const int hb  = blockIdx.x;
    const int i   = blockIdx.y;
    const int b   = blockIdx.z;

    const float* hirow = hi + ((size_t)(b * 256 + i)) * 256;
    ci[tid]     = hirow[tid];
    adjrow[tid] = adj[((size_t)(b * 256 + i)) * 256 + tid];

    const float* hjb = hjp + (size_t)b * 256 * 256;

    const int th = tid & 7;     // h-subtile 0..7
    const int tj = tid >> 3;    // j-subtile 0..31

    float acc[8][8];
    #pragma unroll
    for (int r = 0; r < 8; ++r)
        #pragma unroll
        for (int c = 0; c < 8; ++c) acc[r][c] = 0.f;

    const int kseg = tid & 7;
    const int jb0  = tid >> 3;

    for (int k0 = 0; k0 < 256; k0 += 32) {
        __syncthreads();
        // fill A_s (256 x 32) with relu(ci + hj); coalesced float4 global reads
        #pragma unroll
        for (int it = 0; it < 8; ++it) {
            int j = jb0 + it * 32;
            float4 hv = *(const float4*)(hjb + (size_t)j * 256 + k0 + kseg * 4);
            int kb = k0 + kseg * 4;
            float* dst = A_s + j * 33 + kseg * 4;
            dst[0] = fmaxf(ci[kb + 0] + hv.x, 0.f);
            dst[1] = fmaxf(ci[kb + 1] + hv.y, 0.f);
            dst[2] = fmaxf(ci[kb + 2] + hv.z, 0.f);
            dst[3] = fmaxf(ci[kb + 3] + hv.w, 0.f);
        }
        // fill B_s (32 x 64): 32x64 = 2048 floats, 256 threads x 8 floats each
        {
            int kk = tid >> 3, seg = tid & 7;
            const float* src = W2 + (size_t)(k0 + kk) * 256 + hb * 64 + seg * 8;
            *(float4*)(B_s + kk * 64 + seg * 8)     = *(const float4*)(src);
            *(float4*)(B_s + kk * 64 + seg * 8 + 4) = *(const float4*)(src + 4);
        }
        __syncthreads();
        // 8x8 register tile per thread
        #pragma unroll 4
        for (int kk = 0; kk < 32; ++kk) {
            float a[8];
            #pragma unroll
            for (int r = 0; r < 8; ++r) a[r] = A_s[(tj * 8 + r) * 33 + kk];
            float4 b0 = *(const float4*)(B_s + kk * 64 + th * 8);
            float4 b1 = *(const float4*)(B_s + kk * 64 + th * 8 + 4);
            float bb[8] = {b0.x, b0.y, b0.z, b0.w, b1.x, b1.y, b1.z, b1.w};
            #pragma unroll
            for (int r = 0; r < 8; ++r)
                #pragma unroll
                for (int c = 0; c < 8; ++c)
                    acc[r][c] = fmaf(a[r], bb[c], acc[r][c]);
        }
    }

    // epilogue: bias + relu + adj-weighted reduce over j
    const int hbase = hb * 64 + th * 8;
    float part[8];
    #pragma unroll
    for (int c = 0; c < 8; ++c) {
        float bv = b2[hbase + c];
        float s = 0.f;
        #pragma unroll
        for (int r = 0; r < 8; ++r) {
            float y = fmaxf(acc[r][c] + bv, 0.f);
            s = fmaf(adjrow[tj * 8 + r], y, s);
        }
        part[c] = s;
    }
    __syncthreads();
    float* red = A_s;                 // reuse (needs 32*64 floats)
    #pragma unroll
    for (int c = 0; c < 8; ++c) red[tj * 64 + th * 8 + c] = part[c];
    __syncthreads();
    if (tid < 64) {
        float s = 0.f;
        #pragma unroll
        for (int t = 0; t < 32; ++t) s += red[t * 64 + tid];
        agg[((size_t)(b * 256 + i)) * 256 + hb * 64 + tid] = s;
    }
}

// ---------------- multi-head attention core ---------------------------------
// 8 heads, dh=32, Lq=16, scale = 1/sqrt(256) = 1/16.
// o[b,l, head*32+d] = q[b,l,head*32+d] + sum_j softmax_j(q.k/16) * v[b,j,head*32+d]
// grid: (head=8, b=4); 256 threads. q_bs = batch stride of q (0 => broadcast).
__global__ void attn_kernel(const float* __restrict__ q, int q_bs,
                            const float* __restrict__ k, const float* __restrict__ v,
                            int Lk, float* __restrict__ o)
{
    __shared__ float qs[16 * 32];
    __shared__ float sc[16 * 256];
    const int tid  = threadIdx.x;
    const int head = blockIdx.x;
    const int b    = blockIdx.y;

    const float* qb = q + (size_t)b * q_bs;
    for (int u = tid; u < 512; u += 256) {
        int l = u >> 5, d = u & 31;
        qs[u] = qb[(size_t)l * 256 + head * 32 + d];
    }
    __syncthreads();

    // scores
    {
        int l = tid & 15, jg = tid >> 4;
        const float* kb = k + ((size_t)b * Lk) * 256 + head * 32;
        for (int j = jg; j < Lk; j += 16) {
            const float* kr = kb + (size_t)j * 256;
            float s = 0.f;
            #pragma unroll
            for (int d = 0; d < 32; ++d) s = fmaf(qs[l * 32 + d], kr[d], s);
            sc[l * 256 + j] = s * 0.0625f;
        }
    }
    __syncthreads();

    // softmax per row (rows tiny: 16 rows x Lk)
    if (tid < 16) {
        float m = -1e30f;
        for (int j = 0; j < Lk; ++j) m = fmaxf(m, sc[tid * 256 + j]);
        float sum = 0.f;
        for (int j = 0; j < Lk; ++j) {
            float e = __expf(sc[tid * 256 + j] - m);
            sc[tid * 256 + j] = e;
            sum += e;
        }
        float inv = 1.f / sum;
        for (int j = 0; j < Lk; ++j) sc[tid * 256 + j] *= inv;
    }
    __syncthreads();

    // O = q + A@v
    {
        const float* vb = v + ((size_t)b * Lk) * 256 + head * 32;
        for (int u = tid; u < 512; u += 256) {
            int l = u >> 5, d = u & 31;
            float accv = qs[l * 32 + d];
            for (int j = 0; j < Lk; ++j)
                accv = fmaf(sc[l * 256 + j], vb[(size_t)j * 256 + d], accv);
            o[((size_t)(b * 16 + l)) * 256 + head * 32 + d] = accv;
        }
    }
}

// ---------------- host orchestration ---------------------------------------
static inline void launch_gemm(const float* A, const float* W, const float* bias,
                               const float* res, float* C, int M, int K, int N, int act)
{
    dim3 grid((N + 31) / 32, (M + 31) / 32);
    gemm_kernel<<<grid, 256>>>(A, W, bias, res, C, M, K, N, act);
}

extern "C" void kernel_launch(void* const* d_in, const int* in_sizes, int n_in,
                              void* d_out, int out_size)
{
    (void)in_sizes; (void)n_in; (void)out_size;
    const float* x    = (const float*)d_in[0];
    const float* adj  = (const float*)d_in[1];
    const float* ginW = (const float*)d_in[2];
    const float* ginb = (const float*)d_in[3];
    const float* geW1 = (const float*)d_in[4];
    const float* geb1 = (const float*)d_in[5];
    const float* geW2 = (const float*)d_in[6];
    const float* geb2 = (const float*)d_in[7];
    const float* gnW1 = (const float*)d_in[8];
    const float* gnb1 = (const float*)d_in[9];
    const float* gnW2 = (const float*)d_in[10];
    const float* gnb2 = (const float*)d_in[11];
    const float* goW  = (const float*)d_in[12];
    const float* gob  = (const float*)d_in[13];
    const float* S    = (const float*)d_in[14];
    const float* mWq  = (const float*)d_in[15];
    const float* mbq  = (const float*)d_in[16];
    const float* mWk  = (const float*)d_in[17];
    const float* mbk  = (const float*)d_in[18];
    const float* mWv  = (const float*)d_in[19];
    const float* mbv  = (const float*)d_in[20];
    const float* mWo  = (const float*)d_in[21];
    const float* mbo  = (const float*)d_in[22];
    const float* finW = (const float*)d_in[23];
    const float* finb = (const float*)d_in[24];
    float* out = (float*)d_out;

    float *h, *hi, *hj, *agg, *n1, *n2, *enc, *kb, *vb, *q, *oA, *m1, *m2;
    cudaGetSymbolAddress((void**)&h,   g_h);
    cudaGetSymbolAddress((void**)&hi,  g_hi);
    cudaGetSymbolAddress((void**)&hj,  g_hj);
    cudaGetSymbolAddress((void**)&agg, g_agg);
    cudaGetSymbolAddress((void**)&n1,  g_n1);
    cudaGetSymbolAddress((void**)&n2,  g_n2);
    cudaGetSymbolAddress((void**)&enc, g_enc);
    cudaGetSymbolAddress((void**)&kb,  g_k);
    cudaGetSymbolAddress((void**)&vb,  g_v);
    cudaGetSymbolAddress((void**)&q,   g_q);
    cudaGetSymbolAddress((void**)&oA,  g_oA);
    cudaGetSymbolAddress((void**)&m1,  g_m1);
    cudaGetSymbolAddress((void**)&m2,  g_m2);

    // 1. h = x @ gin_W + gin_b          (B*V=1024, 48) x (48,256)
    launch_gemm(x, ginW, ginb, nullptr, h, 1024, 48, 256, 0);
    // 2. hi = h @ Wi                     (Wi = geW1 rows [0,256))
    launch_gemm(h, geW1, nullptr, nullptr, hi, 1024, 256, 256, 0);
    // 3. hj = h @ Wj + geb1              (Wj = geW1 rows [256,512))
    launch_gemm(h, geW1 + 256 * 256, geb1, nullptr, hj, 1024, 256, 256, 0);
    // 4. fused edge MLP + adjacency contraction -> agg
    edge_kernel<<<dim3(4, 256, 4), 256>>>(hi, hj, geW2, geb2, adj, agg);
    // 5-6. node MLP
    launch_gemm(agg, gnW1, gnb1, nullptr, n1, 1024, 256, 256, 1);
    launch_gemm(n1,  gnW2, gnb2, nullptr, n2, 1024, 256, 256, 1);
    // 7. enc = node @ goW + gob
    launch_gemm(n2, goW, gob, nullptr, enc, 1024, 256, 256, 0);

    // ---- MAB 0: Q = broadcast(S), K = enc (Lk=256) ----
    launch_gemm(S,   mWq, mbq, nullptr, q,  16,   256, 256, 0);
    launch_gemm(enc, mWk, mbk, nullptr, kb, 1024, 256, 256, 0);
    launch_gemm(enc, mWv, mbv, nullptr, vb, 1024, 256, 256, 0);
    attn_kernel<<<dim3(8, 4), 256>>>(q, 0, kb, vb, 256, oA);
    launch_gemm(oA, mWo, mbo, oA, m1, 64, 256, 256, 1);

    // ---- MAB 1: self-attention on m1 (Lq=Lk=16) ----
    launch_gemm(m1, mWq + 65536, mbq + 256, nullptr, q,  64, 256, 256, 0);
    launch_gemm(m1, mWk + 65536, mbk + 256, nullptr, kb, 64, 256, 256, 0);
    launch_gemm(m1, mWv + 65536, mbv + 256, nullptr, vb, 64, 256, 256, 0);
    attn_kernel<<<dim3(8, 4), 256>>>(q, 16 * 256, kb, vb, 16, oA);
    launch_gemm(oA, mWo + 65536, mbo + 256, oA, m2, 64, 256, 256, 1);

    // ---- MAB 2 ----
    launch_gemm(m2, mWq + 2 * 65536, mbq + 2 * 256, nullptr, q,  64, 256, 256, 0);
    launch_gemm(m2, mWk + 2 * 65536, mbk + 2 * 256, nullptr, kb, 64, 256, 256, 0);
    launch_gemm(m2, mWv + 2 * 65536, mbv + 2 * 256, nullptr, vb, 64, 256, 256, 0);
    attn_kernel<<<dim3(8, 4), 256>>>(q, 16 * 256, kb, vb, 16, oA);
    launch_gemm(oA, mWo + 2 * 65536, mbo + 2 * 256, oA, m1, 64, 256, 256, 1);

    // ---- final: out = m1 @ finW + finb -> (B,16,384) == (B,16,12,32) ----
    launch_gemm(m1, finW, finb, nullptr, out, 64, 256, 384, 0);
}

// round 4
// speedup vs baseline: 2.1958x; 2.1958x over previous
#include <cuda_runtime.h>
#include <cstdint>
#include <math.h>
#include <stddef.h>

// ---------------- scratch (device globals; no allocations allowed) ----------
__device__ float g_h  [1024 * 256];
__device__ float g_hi [1024 * 256];
__device__ float g_hj [1024 * 256];
__device__ float g_agg[1024 * 256];
__device__ float g_n1 [1024 * 256];
__device__ float g_n2 [1024 * 256];
__device__ float g_enc[1024 * 256];
__device__ float g_k  [1024 * 256];
__device__ float g_v  [1024 * 256];
__device__ float g_q  [64 * 256];
__device__ float g_oA [64 * 256];
__device__ float g_m1 [64 * 256];
__device__ float g_m2 [64 * 256];
__device__ float g_w2t[256 * 256];   // W2 transposed, tf32-rounded: w2t[n][k] = rnd(W2[k][n])

// ---------------- helpers ----------------------------------------------------
__device__ __forceinline__ uint32_t f2tf32(float f) {
    uint32_t r;
    asm("cvt.rna.tf32.f32 %0, %1;" : "=r"(r) : "f"(f));
    return r;
}
// m16n8k8 tf32 MMA (baseline PTX, sm_80+): D = A@B + D, row.col
__device__ __forceinline__ void mma_tf32(float* c, const uint32_t* a, const uint32_t* bf) {
    asm volatile(
        "mma.sync.aligned.m16n8k8.row.col.f32.tf32.tf32.f32 "
        "{%0,%1,%2,%3}, {%4,%5,%6,%7}, {%8,%9}, {%0,%1,%2,%3};"
        : "+f"(c[0]), "+f"(c[1]), "+f"(c[2]), "+f"(c[3])
        : "r"(a[0]), "r"(a[1]), "r"(a[2]), "r"(a[3]), "r"(bf[0]), "r"(bf[1]));
}

// ---------------- prep: W2 (256x256, row-major [k][n]) -> w2t[n][k], tf32 ----
__global__ void prep_w2t(const float* __restrict__ W2, float* __restrict__ w2t) {
    int n = blockIdx.x, k = threadIdx.x;
    w2t[n * 256 + k] = __uint_as_float(f2tf32(W2[k * 256 + n]));
}

// ---------------- mma.sync fused edge-MLP + adjacency contraction ------------
// Per block (i, b, hh): for jh in {0,1}:
//   A[128j,256k] = tf32(relu(hi[b,i,:] + hj[b, jh*128+j, :]))
//   D = A @ W2[:, hh*128 : hh*128+128]
//   acc[h] += sum_j adj[b,i,jh*128+j] * relu(D[j,h] + b2[hh*128+h])
// 256 threads = 8 warps in 2(jm) x 4(hn); warp tile 64j x 32h.
// SMEM (floats): ci@0[256] adjs@256[256] part@512[256] b2s@768[128] A_s@896[128*68] W_s[128*68]
static constexpr int AS_STRIDE = 68;                 // 64 + 4 pad: conflict-free frags
static constexpr int A_BASE = 896;
static constexpr int W_BASE = 896 + 128 * AS_STRIDE;
static constexpr int EDGE_SMEM_FLOATS = W_BASE + 128 * AS_STRIDE;   // 18304
static constexpr int EDGE_SMEM_BYTES  = EDGE_SMEM_FLOATS * 4;       // 73216

__global__ void __launch_bounds__(256, 2)
edge_mma(const float* __restrict__ hi, const float* __restrict__ hjp,
         const float* __restrict__ w2t, const float* __restrict__ b2,
         const float* __restrict__ adj, float* __restrict__ agg)
{
    extern __shared__ float sm[];
    float* ci   = sm;
    float* adjs = sm + 256;
    float* part = sm + 512;
    float* b2s  = sm + 768;
    float* A_s  = sm + A_BASE;
    float* W_s  = sm + W_BASE;

    const int tid = threadIdx.x, lane = tid & 31, w = tid >> 5;
    const int i = blockIdx.x, b = blockIdx.y, hh = blockIdx.z;
    const size_t row = (size_t)(b * 256 + i) * 256;

    ci[tid]   = hi[row + tid];
    adjs[tid] = adj[row + tid];
    if (tid < 128) b2s[tid] = b2[hh * 128 + tid];

    const int g  = lane >> 2;        // groupID 0..7
    const int tg = lane & 3;         // thread-in-group 0..3
    const int jm = w & 1;            // warp j-half within 128
    const int hn = w >> 1;           // warp h-tile (32 wide)

    const float* hjb = hjp + (size_t)b * 65536;
    const int kq = tid & 15;         // float4 column within 64-k chunk
    const int jr = tid >> 4;         // row 0..15 per fill pass

    float acc = 0.f;                 // tid<128 owns h = tid of this hh-half

    for (int jh = 0; jh < 2; ++jh) {
        float C[4][4][4];
        #pragma unroll
        for (int mt = 0; mt < 4; ++mt)
            #pragma unroll
            for (int nt = 0; nt < 4; ++nt)
                #pragma unroll
                for (int r = 0; r < 4; ++r) C[mt][nt][r] = 0.f;

        for (int kc = 0; kc < 4; ++kc) {
            __syncthreads();   // buffers free (also covers the init fills on first pass)
            const float4 cv = *(const float4*)(ci + kc * 64 + kq * 4);
            #pragma unroll
            for (int p = 0; p < 8; ++p) {
                const int r = p * 16 + jr;      // 0..127 (j for A, n for W)
                float4 hv = *(const float4*)(hjb + (size_t)(jh * 128 + r) * 256 + kc * 64 + kq * 4);
                uint4 o;
                o.x = f2tf32(fmaxf(cv.x + hv.x, 0.f));
                o.y = f2tf32(fmaxf(cv.y + hv.y, 0.f));
                o.z = f2tf32(fmaxf(cv.z + hv.z, 0.f));
                o.w = f2tf32(fmaxf(cv.w + hv.w, 0.f));
                *(uint4*)(A_s + r * AS_STRIDE + kq * 4) = o;
                float4 wv = *(const float4*)(w2t + (size_t)(hh * 128 + r) * 256 + kc * 64 + kq * 4);
                *(float4*)(W_s + r * AS_STRIDE + kq * 4) = wv;
            }
            __syncthreads();

            const uint32_t* ap = (const uint32_t*)A_s;
            const uint32_t* wp = (const uint32_t*)W_s;
            #pragma unroll
            for (int ks = 0; ks < 8; ++ks) {
                uint32_t afr[4][4], bfr[4][2];
                #pragma unroll
                for (int mt = 0; mt < 4; ++mt) {
                    int r0 = (jm * 64 + mt * 16 + g) * AS_STRIDE + ks * 8;
                    afr[mt][0] = ap[r0 + tg];
                    afr[mt][1] = ap[r0 + 8 * AS_STRIDE + tg];
                    afr[mt][2] = ap[r0 + tg + 4];
                    afr[mt][3] = ap[r0 + 8 * AS_STRIDE + tg + 4];
                }
                #pragma unroll
                for (int nt = 0; nt < 4; ++nt) {
                    int r0 = (hn * 32 + nt * 8 + g) * AS_STRIDE + ks * 8;
                    bfr[nt][0] = wp[r0 + tg];
                    bfr[nt][1] = wp[r0 + tg + 4];
                }
                #pragma unroll
                for (int mt = 0; mt < 4; ++mt)
                    #pragma unroll
                    for (int nt = 0; nt < 4; ++nt)
                        mma_tf32(C[mt][nt], afr[mt], bfr[nt]);
            }
        }

        // epilogue for this jh: bias + relu + adj weight, reduce over j
        float ps[4][2];
        #pragma unroll
        for (int nt = 0; nt < 4; ++nt) { ps[nt][0] = 0.f; ps[nt][1] = 0.f; }
        #pragma unroll
        for (int mt = 0; mt < 4; ++mt) {
            const float aj0 = adjs[jh * 128 + jm * 64 + mt * 16 + g];
            const float aj8 = adjs[jh * 128 + jm * 64 + mt * 16 + g + 8];
            #pragma unroll
            for (int nt = 0; nt < 4; ++nt) {
                #pragma unroll
                for (int c = 0; c < 2; ++c) {
                    const float bv = b2s[hn * 32 + nt * 8 + 2 * tg + c];
                    ps[nt][c] += aj0 * fmaxf(C[mt][nt][c]     + bv, 0.f)
                               + aj8 * fmaxf(C[mt][nt][2 + c] + bv, 0.f);
                }
            }
        }
        // reduce over g (lane = 4g+tg): shfl down by 16, 8, 4
        #pragma unroll
        for (int off = 16; off >= 4; off >>= 1)
            #pragma unroll
            for (int nt = 0; nt < 4; ++nt)
                #pragma unroll
                for (int c = 0; c < 2; ++c)
                    ps[nt][c] += __shfl_down_sync(0xffffffffu, ps[nt][c], off);
        if (lane < 4) {
            #pragma unroll
            for (int nt = 0; nt < 4; ++nt)
                #pragma unroll
                for (int c = 0; c < 2; ++c)
                    part[w * 32 + nt * 8 + 2 * lane + c] = ps[nt][c];
        }
        __syncthreads();
        if (tid < 128) {
            const int hn2 = tid >> 5, hl = tid & 31;
            acc += part[(hn2 * 2 + 0) * 32 + hl] + part[(hn2 * 2 + 1) * 32 + hl];
        }
    }

    if (tid < 128) agg[row + hh * 128 + tid] = acc;
}

// ---------------- generic tiled GEMM: C = res? res + act(A@W + b) -----------
__global__ void gemm_kernel(const float* __restrict__ A, const float* __restrict__ W,
                            const float* __restrict__ bias, const float* __restrict__ res,
                            float* __restrict__ C, int M, int K, int N, int act)
{
    __shared__ float As[32 * 33];
    __shared__ float Ws[32 * 33];
    const int tid  = threadIdx.x;
    const int lane = tid & 31;
    const int ty   = tid >> 5;
    const int colB = blockIdx.x * 32;
    const int rowB = blockIdx.y * 32;

    float acc[4] = {0.f, 0.f, 0.f, 0.f};

    for (int k0 = 0; k0 < K; k0 += 32) {
        #pragma unroll
        for (int u = 0; u < 4; ++u) {
            int idx = tid + u * 256;
            int r = idx >> 5, c = idx & 31;
            int gr = rowB + r, gk = k0 + c;
            As[r * 33 + c] = (gr < M && gk < K) ? A[(size_t)gr * K + gk] : 0.f;
            int wk = k0 + r, wc = colB + c;
            Ws[r * 33 + c] = (wk < K && wc < N) ? W[(size_t)wk * N + wc] : 0.f;
        }
        __syncthreads();
        #pragma unroll
        for (int kk = 0; kk < 32; ++kk) {
            float wv = Ws[kk * 33 + lane];
            #pragma unroll
            for (int r = 0; r < 4; ++r)
                acc[r] = fmaf(As[(ty * 4 + r) * 33 + kk], wv, acc[r]);
        }
        __syncthreads();
    }

    int col = colB + lane;
    if (col < N) {
        float bv = bias ? bias[col] : 0.f;
        #pragma unroll
        for (int r = 0; r < 4; ++r) {
            int rowi = rowB + ty * 4 + r;
            if (rowi < M) {
                float v = acc[r] + bv;
                if (act) v = fmaxf(v, 0.f);
                if (res) v += res[(size_t)rowi * N + col];
                C[(size_t)rowi * N + col] = v;
            }
        }
    }
}

// ---------------- multi-head attention core ---------------------------------
__global__ void attn_kernel(const float* __restrict__ q, int q_bs,
                            const float* __restrict__ k, const float* __restrict__ v,
                            int Lk, float* __restrict__ o)
{
    __shared__ float qs[16 * 32];
    __shared__ float sc[16 * 256];
    const int tid  = threadIdx.x;
    const int head = blockIdx.x;
    const int b    = blockIdx.y;

    const float* qb = q + (size_t)b * q_bs;
    for (int u = tid; u < 512; u += 256) {
        int l = u >> 5, d = u & 31;
        qs[u] = qb[(size_t)l * 256 + head * 32 + d];
    }
    __syncthreads();

    {
        int l = tid & 15, jg = tid >> 4;
        const float* kb = k + ((size_t)b * Lk) * 256 + head * 32;
        for (int j = jg; j < Lk; j += 16) {
            const float* kr = kb + (size_t)j * 256;
            float s = 0.f;
            #pragma unroll
            for (int d = 0; d < 32; ++d) s = fmaf(qs[l * 32 + d], kr[d], s);
            sc[l * 256 + j] = s * 0.0625f;
        }
    }
    __syncthreads();

    if (tid < 16) {
        float m = -1e30f;
        for (int j = 0; j < Lk; ++j) m = fmaxf(m, sc[tid * 256 + j]);
        float sum = 0.f;
        for (int j = 0; j < Lk; ++j) {
            float e = __expf(sc[tid * 256 + j] - m);
            sc[tid * 256 + j] = e;
            sum += e;
        }
        float inv = 1.f / sum;
        for (int j = 0; j < Lk; ++j) sc[tid * 256 + j] *= inv;
    }
    __syncthreads();

    {
        const float* vb = v + ((size_t)b * Lk) * 256 + head * 32;
        for (int u = tid; u < 512; u += 256) {
            int l = u >> 5, d = u & 31;
            float accv = qs[l * 32 + d];
            for (int j = 0; j < Lk; ++j)
                accv = fmaf(sc[l * 256 + j], vb[(size_t)j * 256 + d], accv);
            o[((size_t)(b * 16 + l)) * 256 + head * 32 + d] = accv;
        }
    }
}

// ---------------- host orchestration ---------------------------------------
static inline void launch_gemm(const float* A, const float* W, const float* bias,
                               const float* res, float* C, int M, int K, int N, int act)
{
    dim3 grid((N + 31) / 32, (M + 31) / 32);
    gemm_kernel<<<grid, 256>>>(A, W, bias, res, C, M, K, N, act);
}

extern "C" void kernel_launch(void* const* d_in, const int* in_sizes, int n_in,
                              void* d_out, int out_size)
{
    (void)in_sizes; (void)n_in; (void)out_size;
    const float* x    = (const float*)d_in[0];
    const float* adj  = (const float*)d_in[1];
    const float* ginW = (const float*)d_in[2];
    const float* ginb = (const float*)d_in[3];
    const float* geW1 = (const float*)d_in[4];
    const float* geb1 = (const float*)d_in[5];
    const float* geW2 = (const float*)d_in[6];
    const float* geb2 = (const float*)d_in[7];
    const float* gnW1 = (const float*)d_in[8];
    const float* gnb1 = (const float*)d_in[9];
    const float* gnW2 = (const float*)d_in[10];
    const float* gnb2 = (const float*)d_in[11];
    const float* goW  = (const float*)d_in[12];
    const float* gob  = (const float*)d_in[13];
    const float* S    = (const float*)d_in[14];
    const float* mWq  = (const float*)d_in[15];
    const float* mbq  = (const float*)d_in[16];
    const float* mWk  = (const float*)d_in[17];
    const float* mbk  = (const float*)d_in[18];
    const float* mWv  = (const float*)d_in[19];
    const float* mbv  = (const float*)d_in[20];
    const float* mWo  = (const float*)d_in[21];
    const float* mbo  = (const float*)d_in[22];
    const float* finW = (const float*)d_in[23];
    const float* finb = (const float*)d_in[24];
    float* out = (float*)d_out;

    float *h, *hi, *hj, *agg, *n1, *n2, *enc, *kb, *vb, *q, *oA, *m1, *m2, *w2t;
    cudaGetSymbolAddress((void**)&h,   g_h);
    cudaGetSymbolAddress((void**)&hi,  g_hi);
    cudaGetSymbolAddress((void**)&hj,  g_hj);
    cudaGetSymbolAddress((void**)&agg, g_agg);
    cudaGetSymbolAddress((void**)&n1,  g_n1);
    cudaGetSymbolAddress((void**)&n2,  g_n2);
    cudaGetSymbolAddress((void**)&enc, g_enc);
    cudaGetSymbolAddress((void**)&kb,  g_k);
    cudaGetSymbolAddress((void**)&vb,  g_v);
    cudaGetSymbolAddress((void**)&q,   g_q);
    cudaGetSymbolAddress((void**)&oA,  g_oA);
    cudaGetSymbolAddress((void**)&m1,  g_m1);
    cudaGetSymbolAddress((void**)&m2,  g_m2);
    cudaGetSymbolAddress((void**)&w2t, g_w2t);

    cudaFuncSetAttribute(edge_mma, cudaFuncAttributeMaxDynamicSharedMemorySize, EDGE_SMEM_BYTES);

    // 0. prep: transpose+round W2 for the tensor-core edge GEMM
    prep_w2t<<<256, 256>>>(geW2, w2t);
    // 1. h = x @ gin_W + gin_b          (B*V=1024, 48) x (48,256)
    launch_gemm(x, ginW, ginb, nullptr, h, 1024, 48, 256, 0);
    // 2. hi = h @ Wi                     (Wi = geW1 rows [0,256))
    launch_gemm(h, geW1, nullptr, nullptr, hi, 1024, 256, 256, 0);
    // 3. hj = h @ Wj + geb1              (Wj = geW1 rows [256,512))
    launch_gemm(h, geW1 + 256 * 256, geb1, nullptr, hj, 1024, 256, 256, 0);
    // 4. fused edge MLP + adjacency contraction -> agg (mma.sync tf32)
    edge_mma<<<dim3(256, 4, 2), 256, EDGE_SMEM_BYTES>>>(hi, hj, w2t, geb2, adj, agg);
    // 5-6. node MLP
    launch_gemm(agg, gnW1, gnb1, nullptr, n1, 1024, 256, 256, 1);
    launch_gemm(n1,  gnW2, gnb2, nullptr, n2, 1024, 256, 256, 1);
    // 7. enc = node @ goW + gob
    launch_gemm(n2, goW, gob, nullptr, enc, 1024, 256, 256, 0);

    // ---- MAB 0: Q = broadcast(S), K = enc (Lk=256) ----
    launch_gemm(S,   mWq, mbq, nullptr, q,  16,   256, 256, 0);
    launch_gemm(enc, mWk, mbk, nullptr, kb, 1024, 256, 256, 0);
    launch_gemm(enc, mWv, mbv, nullptr, vb, 1024, 256, 256, 0);
    attn_kernel<<<dim3(8, 4), 256>>>(q, 0, kb, vb, 256, oA);
    launch_gemm(oA, mWo, mbo, oA, m1, 64, 256, 256, 1);

    // ---- MAB 1: self-attention on m1 (Lq=Lk=16) ----
    launch_gemm(m1, mWq + 65536, mbq + 256, nullptr, q,  64, 256, 256, 0);
    launch_gemm(m1, mWk + 65536, mbk + 256, nullptr, kb, 64, 256, 256, 0);
    launch_gemm(m1, mWv + 65536, mbv + 256, nullptr, vb, 64, 256, 256, 0);
    attn_kernel<<<dim3(8, 4), 256>>>(q, 16 * 256, kb, vb, 16, oA);
    launch_gemm(oA, mWo + 65536, mbo + 256, oA, m2, 64, 256, 256, 1);

    // ---- MAB 2 ----
    launch_gemm(m2, mWq + 2 * 65536, mbq + 2 * 256, nullptr, q,  64, 256, 256, 0);
    launch_gemm(m2, mWk + 2 * 65536, mbk + 2 * 256, nullptr, kb, 64, 256, 256, 0);
    launch_gemm(m2, mWv + 2 * 65536, mbv + 2 * 256, nullptr, vb, 64, 256, 256, 0);
    attn_kernel<<<dim3(8, 4), 256>>>(q, 16 * 256, kb, vb, 16, oA);
    launch_gemm(oA, mWo + 2 * 65536, mbo + 2 * 256, oA, m1, 64, 256, 256, 1);

    // ---- final: out = m1 @ finW + finb -> (B,16,384) == (B,16,12,32) ----
    launch_gemm(m1, finW, finb, nullptr, out, 64, 256, 384, 0);
}